// round 11
// baseline (speedup 1.0000x reference)
#include <cuda_runtime.h>
#include <cuda_fp16.h>
#include <cstdint>

#define NB     2048
#define NCELLS 96
#define NLINES 24
#define ND     512
#define NROWS  (NB * NLINES)   // 49152

// -------- scratch (device globals; allocation-free) --------
__device__ __align__(1024) __half g_LC[(size_t)NROWS * ND];
__device__ __align__(1024) __half g_GC[(size_t)NB * ND];
__device__ __align__(1024) __half g_H [(size_t)NROWS * ND];
__device__ __align__(1024) __half g_P [(size_t)NROWS * ND];
__device__ __align__(1024) __half g_Hg[(size_t)NB * ND];
__device__ __align__(1024) __half g_S [(size_t)NB * ND];
__device__ __align__(1024) __half g_Wt[4][(size_t)ND * ND];   // weights transposed [n][k] fp16

// ============================================================
// prep: blocks [0,1024): weight transpose fp32[k][n] -> fp16[n][k]
//       blocks [1024,2048): reduction, 2 batches per block
// ============================================================
__global__ void __launch_bounds__(256)
prep_kernel(const float* __restrict__ x,
            const float* __restrict__ W1, const float* __restrict__ W2,
            const float* __restrict__ G1, const float* __restrict__ G2)
{
    __shared__ float tile[32][33];
    const int tid = threadIdx.x;

    if (blockIdx.x < 1024) {
        const int z   = blockIdx.x >> 8;
        const int blk = blockIdx.x & 255;
        const float* W = (z == 0) ? W1 : (z == 1) ? W2 : (z == 2) ? G1 : G2;
        __half* Wt = &g_Wt[z][0];
        const int n0 = (blk & 15) * 32, k0 = (blk >> 4) * 32;
        const int tx = tid & 31, ty = tid >> 5;
        #pragma unroll
        for (int i = ty; i < 32; i += 8)
            tile[i][tx] = W[(size_t)(k0 + i) * ND + n0 + tx];
        __syncthreads();
        #pragma unroll
        for (int i = ty; i < 32; i += 8)
            Wt[(size_t)(n0 + i) * ND + k0 + tx] = __float2half(tile[tx][i]);
        return;
    }

    const int b = (blockIdx.x - 1024) * 2 + (tid >> 7);
    const int t = tid & 127;
    const float4* xr = reinterpret_cast<const float4*>(x) + (size_t)b * NCELLS * (ND/4) + t;

    float tx_ = 0.f, ty_ = 0.f, tz_ = 0.f, tw_ = 0.f;
    #pragma unroll 4
    for (int g = 0; g < NLINES; g++) {
        float4 v0 = __ldcs(&xr[(g*4 + 0) * (ND/4)]);
        float4 v1 = __ldcs(&xr[(g*4 + 1) * (ND/4)]);
        float4 v2 = __ldcs(&xr[(g*4 + 2) * (ND/4)]);
        float4 v3 = __ldcs(&xr[(g*4 + 3) * (ND/4)]);
        float sx = v0.x + v1.x + v2.x + v3.x;
        float sy = v0.y + v1.y + v2.y + v3.y;
        float sz = v0.z + v1.z + v2.z + v3.z;
        float sw = v0.w + v1.w + v2.w + v3.w;
        __half2 lo = __floats2half2_rn(sx * 0.25f, sy * 0.25f);
        __half2 hi = __floats2half2_rn(sz * 0.25f, sw * 0.25f);
        uint2 pk = make_uint2(*(uint32_t*)&lo, *(uint32_t*)&hi);
        *reinterpret_cast<uint2*>(&g_LC[((size_t)b * NLINES + g) * ND + t * 4]) = pk;
        tx_ += sx; ty_ += sy; tz_ += sz; tw_ += sw;
    }
    const float inv96 = 1.0f / 96.0f;
    __half2 lo = __floats2half2_rn(tx_ * inv96, ty_ * inv96);
    __half2 hi = __floats2half2_rn(tz_ * inv96, tw_ * inv96);
    uint2 pk = make_uint2(*(uint32_t*)&lo, *(uint32_t*)&hi);
    *reinterpret_cast<uint2*>(&g_GC[(size_t)b * ND + t * 4]) = pk;
}

// ============================================================
// FP16 GEMM: BM=128 BN=64 BK=64, 4-stage cp.async, 256 threads,
// 8 warps (4m x 2n), warp tile 32x32, ldmatrix + m16n8k16.
// Two problems per launch (blockIdx.x split).
// ============================================================
__device__ __forceinline__ float mish_f(float v)
{
    float t   = __expf(v);
    float num = t * (t + 2.0f);
    float r   = v * __fdividef(num, num + 2.0f);
    return (v > 30.0f) ? v : r;
}

#define BK       64
#define SPAD     72                        // 144B row stride (conflict-free ldmatrix)
#define TA_BYTES (128 * SPAD * 2)          // 18432
#define TB_BYTES (64  * SPAD * 2)          // 9216
#define STAGE_B  (TA_BYTES + TB_BYTES)     // 27648
#define NSTAGE   4
#define SMEM_B   (NSTAGE * STAGE_B)        // 110592

#define LDMX4(r0, r1, r2, r3, addr) \
    asm volatile("ldmatrix.sync.aligned.m8n8.x4.shared.b16 {%0,%1,%2,%3}, [%4];" \
                 : "=r"(r0), "=r"(r1), "=r"(r2), "=r"(r3) : "r"(addr))

#define MMA16816(acc, af, b0, b1) \
    asm volatile("mma.sync.aligned.m16n8k16.row.col.f32.f16.f16.f32 " \
                 "{%0,%1,%2,%3},{%4,%5,%6,%7},{%8,%9},{%0,%1,%2,%3};\n" \
                 : "+f"((acc)[0]), "+f"((acc)[1]), "+f"((acc)[2]), "+f"((acc)[3]) \
                 : "r"((af)[0]), "r"((af)[1]), "r"((af)[2]), "r"((af)[3]), \
                   "r"(b0), "r"(b1))

template<bool MISH>
__global__ void __launch_bounds__(256, 2)
gemm_kernel(const __half* __restrict__ A0, const __half* __restrict__ B0,
            const float* __restrict__ bias0, __half* __restrict__ C0, int mb0,
            const __half* __restrict__ A1, const __half* __restrict__ B1,
            const float* __restrict__ bias1, __half* __restrict__ C1)
{
    extern __shared__ __half smem[];

    const __half* A;  const __half* Bt;  const float* bias;  __half* Cout;
    size_t bm;
    if ((int)blockIdx.x < mb0) { A = A0; Bt = B0; bias = bias0; Cout = C0; bm = (size_t)blockIdx.x * 128; }
    else                       { A = A1; Bt = B1; bias = bias1; Cout = C1; bm = (size_t)(blockIdx.x - mb0) * 128; }
    const int bn = blockIdx.y * 64;

    const int tid  = threadIdx.x;
    const int lane = tid & 31;
    const int warp = tid >> 5;
    const int wm = (warp >> 1) * 32;   // 4 warps over M (128)
    const int wn = (warp & 1) * 32;    // 2 warps over N (64)

    const uint32_t sbase = (uint32_t)__cvta_generic_to_shared(smem);
    auto load_chunk = [&](int kc, int buf) {
        const uint32_t st = sbase + buf * STAGE_B;
        #pragma unroll
        for (int j = 0; j < 4; j++) {                       // A: 128 rows x 8 segs
            const int idx = tid + 256 * j;
            const int row = idx >> 3, seg = idx & 7;
            uint32_t dst = st + row * (SPAD * 2) + seg * 16;
            const __half* src = A + (bm + row) * (size_t)ND + kc * BK + seg * 8;
            asm volatile("cp.async.cg.shared.global [%0],[%1],16;\n" :: "r"(dst), "l"(src));
        }
        #pragma unroll
        for (int j = 0; j < 2; j++) {                       // B: 64 rows x 8 segs
            const int idx = tid + 256 * j;
            const int row = idx >> 3, seg = idx & 7;
            uint32_t dst = st + TA_BYTES + row * (SPAD * 2) + seg * 16;
            const __half* src = Bt + (size_t)(bn + row) * ND + kc * BK + seg * 8;
            asm volatile("cp.async.cg.shared.global [%0],[%1],16;\n" :: "r"(dst), "l"(src));
        }
        asm volatile("cp.async.commit_group;\n" ::);
    };

    uint32_t aoff[2], boff[2];
    #pragma unroll
    for (int mt = 0; mt < 2; mt++)
        aoff[mt] = (wm + mt * 16 + (lane & 15)) * (SPAD * 2) + ((lane >> 4) * 8) * 2;
    #pragma unroll
    for (int p = 0; p < 2; p++)
        boff[p] = TA_BYTES +
                  (wn + p * 16 + ((lane >> 4) << 3) + (lane & 7)) * (SPAD * 2) +
                  (((lane >> 3) & 1) * 8) * 2;

    float acc[2][4][4];
    #pragma unroll
    for (int mt = 0; mt < 2; mt++)
        #pragma unroll
        for (int nt = 0; nt < 4; nt++)
            #pragma unroll
            for (int k = 0; k < 4; k++) acc[mt][nt][k] = 0.f;

    load_chunk(0, 0);
    load_chunk(1, 1);
    load_chunk(2, 2);

    for (int i = 0; i < 8; i++) {
        if      (i < 6)  asm volatile("cp.async.wait_group 2;\n" ::);
        else if (i == 6) asm volatile("cp.async.wait_group 1;\n" ::);
        else             asm volatile("cp.async.wait_group 0;\n" ::);
        __syncthreads();
        if (i + 3 < 8) load_chunk(i + 3, (i + 3) & 3);
        const uint32_t st = sbase + (i & 3) * STAGE_B;

        // double-buffered fragments over the 4 k-steps
        uint32_t a[2][2][4], b[2][2][4];
        #pragma unroll
        for (int mt = 0; mt < 2; mt++)
            LDMX4(a[0][mt][0], a[0][mt][1], a[0][mt][2], a[0][mt][3], st + aoff[mt]);
        #pragma unroll
        for (int p = 0; p < 2; p++)
            LDMX4(b[0][p][0], b[0][p][1], b[0][p][2], b[0][p][3], st + boff[p]);

        #pragma unroll
        for (int kk = 0; kk < 4; kk++) {
            const int cur = kk & 1, nxt = cur ^ 1;
            if (kk < 3) {
                const uint32_t kb = (kk + 1) * 32;
                #pragma unroll
                for (int mt = 0; mt < 2; mt++)
                    LDMX4(a[nxt][mt][0], a[nxt][mt][1], a[nxt][mt][2], a[nxt][mt][3],
                          st + aoff[mt] + kb);
                #pragma unroll
                for (int p = 0; p < 2; p++)
                    LDMX4(b[nxt][p][0], b[nxt][p][1], b[nxt][p][2], b[nxt][p][3],
                          st + boff[p] + kb);
            }
            #pragma unroll
            for (int mt = 0; mt < 2; mt++)
                #pragma unroll
                for (int p = 0; p < 2; p++) {
                    MMA16816(acc[mt][2*p],     a[cur][mt], b[cur][p][0], b[cur][p][1]);
                    MMA16816(acc[mt][2*p + 1], a[cur][mt], b[cur][p][2], b[cur][p][3]);
                }
        }
    }

    // ---- epilogue: bias (+fast mish), fp16 stores ----
    const int fr = lane >> 2;
    const int fc = (lane & 3) * 2;
    #pragma unroll
    for (int mt = 0; mt < 2; mt++) {
        #pragma unroll
        for (int nt = 0; nt < 4; nt++) {
            const size_t r0 = bm + wm + mt * 16 + fr;
            const int    c0 = bn + wn + nt * 8 + fc;
            const float bv0 = bias[c0], bv1 = bias[c0 + 1];
            float v0 = acc[mt][nt][0] + bv0;
            float v1 = acc[mt][nt][1] + bv1;
            float v2 = acc[mt][nt][2] + bv0;
            float v3 = acc[mt][nt][3] + bv1;
            if (MISH) { v0 = mish_f(v0); v1 = mish_f(v1); v2 = mish_f(v2); v3 = mish_f(v3); }
            *reinterpret_cast<__half2*>(&Cout[r0 * ND + c0])       = __floats2half2_rn(v0, v1);
            *reinterpret_cast<__half2*>(&Cout[(r0 + 8) * ND + c0]) = __floats2half2_rn(v2, v3);
        }
    }
}

// ============================================================
// LN: out[b,m,:] = LayerNorm(x[b,m,:] + P[b,m/4,:] + S[b,:])
// ============================================================
__global__ void __launch_bounds__(256)
ln_kernel(const float* __restrict__ x,
          const float* __restrict__ gamma,
          const float* __restrict__ beta,
          float* __restrict__ out)
{
    const int warp = threadIdx.x >> 5;
    const int lane = threadIdx.x & 31;
    const int row  = blockIdx.x * 8 + warp;      // b*96 + m
    const int b    = row / NCELLS;
    const int m    = row - b * NCELLS;
    const int line = m >> 2;

    const float4* xr = reinterpret_cast<const float4*>(x) + (size_t)row * (ND/4);
    const uint2*  pr = reinterpret_cast<const uint2*>(g_P + ((size_t)b * NLINES + line) * ND);
    const uint2*  sr = reinterpret_cast<const uint2*>(g_S + (size_t)b * ND);

    float4 v[4];
    float s = 0.f, sq = 0.f;
    #pragma unroll
    for (int j = 0; j < 4; j++) {
        const int t = lane + j * 32;
        float4 xv = __ldcs(&xr[t]);
        uint2 pu = pr[t], su = sr[t];
        float2 p01 = __half22float2(*(__half2*)&pu.x);
        float2 p23 = __half22float2(*(__half2*)&pu.y);
        float2 s01 = __half22float2(*(__half2*)&su.x);
        float2 s23 = __half22float2(*(__half2*)&su.y);
        float4 w = make_float4(xv.x + p01.x + s01.x, xv.y + p01.y + s01.y,
                               xv.z + p23.x + s23.x, xv.w + p23.y + s23.y);
        v[j] = w;
        s  += w.x + w.y + w.z + w.w;
        sq += w.x*w.x + w.y*w.y + w.z*w.z + w.w*w.w;
    }
    #pragma unroll
    for (int o = 16; o; o >>= 1) {
        s  += __shfl_xor_sync(0xffffffffu, s,  o);
        sq += __shfl_xor_sync(0xffffffffu, sq, o);
    }
    const float mean = s * (1.0f / ND);
    const float var  = sq * (1.0f / ND) - mean * mean;
    const float inv  = rsqrtf(var + 1e-5f);

    float4* orow = reinterpret_cast<float4*>(out) + (size_t)row * (ND/4);
    #pragma unroll
    for (int j = 0; j < 4; j++) {
        const int t = lane + j * 32;
        float4 gv = reinterpret_cast<const float4*>(gamma)[t];
        float4 bv = reinterpret_cast<const float4*>(beta)[t];
        float4 o;
        o.x = (v[j].x - mean) * inv * gv.x + bv.x;
        o.y = (v[j].y - mean) * inv * gv.y + bv.y;
        o.z = (v[j].z - mean) * inv * gv.z + bv.z;
        o.w = (v[j].w - mean) * inv * gv.w + bv.w;
        __stcs(&orow[t], o);
    }
}

// ============================================================
// launch
// ============================================================
extern "C" void kernel_launch(void* const* d_in, const int* in_sizes, int n_in,
                              void* d_out, int out_size)
{
    const float* x     = (const float*)d_in[0];
    const float* W1    = (const float*)d_in[2];
    const float* b1    = (const float*)d_in[3];
    const float* W2    = (const float*)d_in[4];
    const float* b2    = (const float*)d_in[5];
    const float* G1    = (const float*)d_in[6];
    const float* gb1   = (const float*)d_in[7];
    const float* G2    = (const float*)d_in[8];
    const float* gb2   = (const float*)d_in[9];
    const float* gamma = (const float*)d_in[10];
    const float* beta  = (const float*)d_in[11];
    float* out = (float*)d_out;

    __half *pLC, *pGC, *pH, *pP, *pHg, *pS, *pWt;
    cudaGetSymbolAddress((void**)&pLC, g_LC);
    cudaGetSymbolAddress((void**)&pGC, g_GC);
    cudaGetSymbolAddress((void**)&pH,  g_H);
    cudaGetSymbolAddress((void**)&pP,  g_P);
    cudaGetSymbolAddress((void**)&pHg, g_Hg);
    cudaGetSymbolAddress((void**)&pS,  g_S);
    cudaGetSymbolAddress((void**)&pWt, g_Wt);
    __half* pW1t = pWt + 0 * (size_t)ND * ND;
    __half* pW2t = pWt + 1 * (size_t)ND * ND;
    __half* pG1t = pWt + 2 * (size_t)ND * ND;
    __half* pG2t = pWt + 3 * (size_t)ND * ND;

    cudaFuncSetAttribute(gemm_kernel<true >, cudaFuncAttributeMaxDynamicSharedMemorySize, SMEM_B);
    cudaFuncSetAttribute(gemm_kernel<false>, cudaFuncAttributeMaxDynamicSharedMemorySize, SMEM_B);

    // 1) weights + reductions, one launch
    prep_kernel<<<2048, 256>>>(x, W1, W2, G1, G2);

    // 2) stage 1 (mish): big + small fused
    const int mb_big = NROWS / 128, mb_sm = NB / 128;   // 384, 16
    gemm_kernel<true ><<<dim3(mb_big + mb_sm, 8), 256, SMEM_B>>>(
        pLC, pW1t, b1, pH, mb_big, pGC, pG1t, gb1, pHg);

    // 3) stage 2 (linear): big + small fused
    gemm_kernel<false><<<dim3(mb_big + mb_sm, 8), 256, SMEM_B>>>(
        pH, pW2t, b2, pP, mb_big, pHg, pG2t, gb2, pS);

    // 4) combine + LayerNorm
    ln_kernel<<<NB * NCELLS / 8, 256>>>(x, gamma, beta, out);
}

// round 13
// speedup vs baseline: 1.0425x; 1.0425x over previous
#include <cuda_runtime.h>
#include <cuda_fp16.h>
#include <cstdint>

#define NB     2048
#define NCELLS 96
#define NLINES 24
#define ND     512
#define NROWS  (NB * NLINES)   // 49152

// -------- scratch (device globals; allocation-free) --------
__device__ __align__(1024) __half g_LC[(size_t)NROWS * ND];
__device__ __align__(1024) __half g_GC[(size_t)NB * ND];
__device__ __align__(1024) __half g_H [(size_t)NROWS * ND];
__device__ __align__(1024) __half g_P [(size_t)NROWS * ND];
__device__ __align__(1024) __half g_Hg[(size_t)NB * ND];
__device__ __align__(1024) __half g_S [(size_t)NB * ND];
__device__ __align__(1024) __half g_Wt[4][(size_t)ND * ND];   // weights transposed [n][k] fp16

// ============================================================
// prep: blocks [0,1024): weight transpose fp32[k][n] -> fp16[n][k]
//       blocks [1024,2048): reduction, 2 batches per block
// ============================================================
__global__ void __launch_bounds__(256)
prep_kernel(const float* __restrict__ x,
            const float* __restrict__ W1, const float* __restrict__ W2,
            const float* __restrict__ G1, const float* __restrict__ G2)
{
    __shared__ float tile[32][33];
    const int tid = threadIdx.x;

    if (blockIdx.x < 1024) {
        const int z   = blockIdx.x >> 8;
        const int blk = blockIdx.x & 255;
        const float* W = (z == 0) ? W1 : (z == 1) ? W2 : (z == 2) ? G1 : G2;
        __half* Wt = &g_Wt[z][0];
        const int n0 = (blk & 15) * 32, k0 = (blk >> 4) * 32;
        const int tx = tid & 31, ty = tid >> 5;
        #pragma unroll
        for (int i = ty; i < 32; i += 8)
            tile[i][tx] = W[(size_t)(k0 + i) * ND + n0 + tx];
        __syncthreads();
        #pragma unroll
        for (int i = ty; i < 32; i += 8)
            Wt[(size_t)(n0 + i) * ND + k0 + tx] = __float2half(tile[tx][i]);
        return;
    }

    const int b = (blockIdx.x - 1024) * 2 + (tid >> 7);
    const int t = tid & 127;
    const float4* xr = reinterpret_cast<const float4*>(x) + (size_t)b * NCELLS * (ND/4) + t;

    float tx_ = 0.f, ty_ = 0.f, tz_ = 0.f, tw_ = 0.f;
    #pragma unroll 4
    for (int g = 0; g < NLINES; g++) {
        float4 v0 = __ldcs(&xr[(g*4 + 0) * (ND/4)]);
        float4 v1 = __ldcs(&xr[(g*4 + 1) * (ND/4)]);
        float4 v2 = __ldcs(&xr[(g*4 + 2) * (ND/4)]);
        float4 v3 = __ldcs(&xr[(g*4 + 3) * (ND/4)]);
        float sx = v0.x + v1.x + v2.x + v3.x;
        float sy = v0.y + v1.y + v2.y + v3.y;
        float sz = v0.z + v1.z + v2.z + v3.z;
        float sw = v0.w + v1.w + v2.w + v3.w;
        __half2 lo = __floats2half2_rn(sx * 0.25f, sy * 0.25f);
        __half2 hi = __floats2half2_rn(sz * 0.25f, sw * 0.25f);
        uint2 pk = make_uint2(*(uint32_t*)&lo, *(uint32_t*)&hi);
        *reinterpret_cast<uint2*>(&g_LC[((size_t)b * NLINES + g) * ND + t * 4]) = pk;
        tx_ += sx; ty_ += sy; tz_ += sz; tw_ += sw;
    }
    const float inv96 = 1.0f / 96.0f;
    __half2 lo = __floats2half2_rn(tx_ * inv96, ty_ * inv96);
    __half2 hi = __floats2half2_rn(tz_ * inv96, tw_ * inv96);
    uint2 pk = make_uint2(*(uint32_t*)&lo, *(uint32_t*)&hi);
    *reinterpret_cast<uint2*>(&g_GC[(size_t)b * ND + t * 4]) = pk;
}

// ============================================================
// FP16 GEMM (R10 champion config): BM=128 BN=128 BK=64,
// 3-stage cp.async, 256 threads, 8 warps (4m x 2n), warp 32x64,
// ldmatrix + m16n8k16, pipelined frags. Two problems per launch.
// PDL: grid-sync before loads, trigger after mainloop.
// ============================================================
__device__ __forceinline__ float mish_f(float v)
{
    float t   = __expf(v);
    float num = t * (t + 2.0f);
    float r   = v * __fdividef(num, num + 2.0f);
    return (v > 30.0f) ? v : r;
}

#define BK      64
#define SPAD    72
#define TILE_H  (128 * SPAD)
#define STAGE_H (2 * TILE_H)
#define NSTAGE  3
#define SMEM_B  (NSTAGE * STAGE_H * 2)    // 110592 bytes

#define LDMX4(r0, r1, r2, r3, addr) \
    asm volatile("ldmatrix.sync.aligned.m8n8.x4.shared.b16 {%0,%1,%2,%3}, [%4];" \
                 : "=r"(r0), "=r"(r1), "=r"(r2), "=r"(r3) : "r"(addr))

#define MMA16816(acc, af, b0, b1) \
    asm volatile("mma.sync.aligned.m16n8k16.row.col.f32.f16.f16.f32 " \
                 "{%0,%1,%2,%3},{%4,%5,%6,%7},{%8,%9},{%0,%1,%2,%3};\n" \
                 : "+f"((acc)[0]), "+f"((acc)[1]), "+f"((acc)[2]), "+f"((acc)[3]) \
                 : "r"((af)[0]), "r"((af)[1]), "r"((af)[2]), "r"((af)[3]), \
                   "r"(b0), "r"(b1))

template<bool MISH>
__global__ void __launch_bounds__(256, 2)
gemm_kernel(const __half* __restrict__ A0, const __half* __restrict__ B0,
            const float* __restrict__ bias0, __half* __restrict__ C0, int mb0,
            const __half* __restrict__ A1, const __half* __restrict__ B1,
            const float* __restrict__ bias1, __half* __restrict__ C1)
{
    extern __shared__ __half smem[];

    const __half* A;  const __half* Bt;  const float* bias;  __half* Cout;
    size_t bm;
    if ((int)blockIdx.x < mb0) { A = A0; Bt = B0; bias = bias0; Cout = C0; bm = (size_t)blockIdx.x * 128; }
    else                       { A = A1; Bt = B1; bias = bias1; Cout = C1; bm = (size_t)(blockIdx.x - mb0) * 128; }
    const int bn = blockIdx.y * 128;

    const int tid  = threadIdx.x;
    const int lane = tid & 31;
    const int warp = tid >> 5;
    const int wm = (warp >> 1) * 32;
    const int wn = (warp & 1) * 64;

    const uint32_t sbase = (uint32_t)__cvta_generic_to_shared(smem);
    auto load_chunk = [&](int kc, int buf) {
        const uint32_t st = sbase + buf * (STAGE_H * 2);
        #pragma unroll
        for (int j = 0; j < 4; j++) {
            const int idx = tid + 256 * j;
            const int row = idx >> 3, seg = idx & 7;
            uint32_t dst = st + row * (SPAD * 2) + seg * 16;
            const __half* src = A + (bm + row) * (size_t)ND + kc * BK + seg * 8;
            asm volatile("cp.async.cg.shared.global [%0],[%1],16;\n" :: "r"(dst), "l"(src));
        }
        #pragma unroll
        for (int j = 0; j < 4; j++) {
            const int idx = tid + 256 * j;
            const int row = idx >> 3, seg = idx & 7;
            uint32_t dst = st + (TILE_H * 2) + row * (SPAD * 2) + seg * 16;
            const __half* src = Bt + (size_t)(bn + row) * ND + kc * BK + seg * 8;
            asm volatile("cp.async.cg.shared.global [%0],[%1],16;\n" :: "r"(dst), "l"(src));
        }
        asm volatile("cp.async.commit_group;\n" ::);
    };

    uint32_t aoff[2], boff[4];
    #pragma unroll
    for (int mt = 0; mt < 2; mt++)
        aoff[mt] = (wm + mt * 16 + (lane & 15)) * (SPAD * 2) + ((lane >> 4) * 8) * 2;
    #pragma unroll
    for (int p = 0; p < 4; p++)
        boff[p] = (TILE_H * 2) +
                  (wn + p * 16 + ((lane >> 4) << 3) + (lane & 7)) * (SPAD * 2) +
                  (((lane >> 3) & 1) * 8) * 2;

    float acc[2][8][4];
    #pragma unroll
    for (int mt = 0; mt < 2; mt++)
        #pragma unroll
        for (int nt = 0; nt < 8; nt++)
            #pragma unroll
            for (int k = 0; k < 4; k++) acc[mt][nt][k] = 0.f;

    // wait for producer kernel's outputs (A operand; weights via transitivity)
    cudaGridDependencySynchronize();

    load_chunk(0, 0);
    load_chunk(1, 1);

    for (int i = 0; i < 8; i++) {
        if (i < 7) asm volatile("cp.async.wait_group 1;\n" ::);
        else       asm volatile("cp.async.wait_group 0;\n" ::);
        __syncthreads();
        if (i + 2 < 8) load_chunk(i + 2, (i + 2) % 3);
        const uint32_t st = sbase + (i % 3) * (STAGE_H * 2);

        uint32_t a[2][2][4], b[2][4][4];
        #pragma unroll
        for (int mt = 0; mt < 2; mt++)
            LDMX4(a[0][mt][0], a[0][mt][1], a[0][mt][2], a[0][mt][3], st + aoff[mt]);
        #pragma unroll
        for (int p = 0; p < 4; p++)
            LDMX4(b[0][p][0], b[0][p][1], b[0][p][2], b[0][p][3], st + boff[p]);

        #pragma unroll
        for (int kk = 0; kk < 4; kk++) {
            const int cur = kk & 1, nxt = cur ^ 1;
            if (kk < 3) {
                const uint32_t kb = (kk + 1) * 32;
                #pragma unroll
                for (int mt = 0; mt < 2; mt++)
                    LDMX4(a[nxt][mt][0], a[nxt][mt][1], a[nxt][mt][2], a[nxt][mt][3],
                          st + aoff[mt] + kb);
                #pragma unroll
                for (int p = 0; p < 4; p++)
                    LDMX4(b[nxt][p][0], b[nxt][p][1], b[nxt][p][2], b[nxt][p][3],
                          st + boff[p] + kb);
            }
            #pragma unroll
            for (int mt = 0; mt < 2; mt++)
                #pragma unroll
                for (int p = 0; p < 4; p++) {
                    MMA16816(acc[mt][2*p],     a[cur][mt], b[cur][p][0], b[cur][p][1]);
                    MMA16816(acc[mt][2*p + 1], a[cur][mt], b[cur][p][2], b[cur][p][3]);
                }
        }
    }

    // allow the next kernel to launch and run its pre-sync prologue
    // while we run the epilogue (it grid-syncs before reading our output)
    cudaTriggerProgrammaticLaunchCompletion();

    // ---- epilogue: bias (+fast mish), fp16 stores ----
    const int fr = lane >> 2;
    const int fc = (lane & 3) * 2;
    #pragma unroll
    for (int mt = 0; mt < 2; mt++) {
        #pragma unroll
        for (int nt = 0; nt < 8; nt++) {
            const size_t r0 = bm + wm + mt * 16 + fr;
            const int    c0 = bn + wn + nt * 8 + fc;
            const float bv0 = bias[c0], bv1 = bias[c0 + 1];
            float v0 = acc[mt][nt][0] + bv0;
            float v1 = acc[mt][nt][1] + bv1;
            float v2 = acc[mt][nt][2] + bv0;
            float v3 = acc[mt][nt][3] + bv1;
            if (MISH) { v0 = mish_f(v0); v1 = mish_f(v1); v2 = mish_f(v2); v3 = mish_f(v3); }
            *reinterpret_cast<__half2*>(&Cout[r0 * ND + c0])       = __floats2half2_rn(v0, v1);
            *reinterpret_cast<__half2*>(&Cout[(r0 + 8) * ND + c0]) = __floats2half2_rn(v2, v3);
        }
    }
}

// ============================================================
// LN: out[b,m,:] = LayerNorm(x[b,m,:] + P[b,m/4,:] + S[b,:])
// PDL: prefetch x (independent of predecessors) pre-sync,
// then grid-sync, then read P/S.
// ============================================================
__global__ void __launch_bounds__(256)
ln_kernel(const float* __restrict__ x,
          const float* __restrict__ gamma,
          const float* __restrict__ beta,
          float* __restrict__ out)
{
    const int warp = threadIdx.x >> 5;
    const int lane = threadIdx.x & 31;
    const int row  = blockIdx.x * 8 + warp;      // b*96 + m
    const int b    = row / NCELLS;
    const int m    = row - b * NCELLS;
    const int line = m >> 2;

    const float4* xr = reinterpret_cast<const float4*>(x) + (size_t)row * (ND/4);

    // prefetch x before waiting on gemm2 (x depends on nothing)
    float4 xv[4];
    #pragma unroll
    for (int j = 0; j < 4; j++)
        xv[j] = __ldcs(&xr[lane + j * 32]);

    cudaGridDependencySynchronize();

    const uint2* pr = reinterpret_cast<const uint2*>(g_P + ((size_t)b * NLINES + line) * ND);
    const uint2* sr = reinterpret_cast<const uint2*>(g_S + (size_t)b * ND);

    float4 v[4];
    float s = 0.f, sq = 0.f;
    #pragma unroll
    for (int j = 0; j < 4; j++) {
        const int t = lane + j * 32;
        uint2 pu = pr[t], su = sr[t];
        float2 p01 = __half22float2(*(__half2*)&pu.x);
        float2 p23 = __half22float2(*(__half2*)&pu.y);
        float2 s01 = __half22float2(*(__half2*)&su.x);
        float2 s23 = __half22float2(*(__half2*)&su.y);
        float4 w = make_float4(xv[j].x + p01.x + s01.x, xv[j].y + p01.y + s01.y,
                               xv[j].z + p23.x + s23.x, xv[j].w + p23.y + s23.y);
        v[j] = w;
        s  += w.x + w.y + w.z + w.w;
        sq += w.x*w.x + w.y*w.y + w.z*w.z + w.w*w.w;
    }
    #pragma unroll
    for (int o = 16; o; o >>= 1) {
        s  += __shfl_xor_sync(0xffffffffu, s,  o);
        sq += __shfl_xor_sync(0xffffffffu, sq, o);
    }
    const float mean = s * (1.0f / ND);
    const float var  = sq * (1.0f / ND) - mean * mean;
    const float inv  = rsqrtf(var + 1e-5f);

    float4* orow = reinterpret_cast<float4*>(out) + (size_t)row * (ND/4);
    #pragma unroll
    for (int j = 0; j < 4; j++) {
        const int t = lane + j * 32;
        float4 gv = reinterpret_cast<const float4*>(gamma)[t];
        float4 bv = reinterpret_cast<const float4*>(beta)[t];
        float4 o;
        o.x = (v[j].x - mean) * inv * gv.x + bv.x;
        o.y = (v[j].y - mean) * inv * gv.y + bv.y;
        o.z = (v[j].z - mean) * inv * gv.z + bv.z;
        o.w = (v[j].w - mean) * inv * gv.w + bv.w;
        __stcs(&orow[t], o);
    }
}

// ============================================================
// launch
// ============================================================
extern "C" void kernel_launch(void* const* d_in, const int* in_sizes, int n_in,
                              void* d_out, int out_size)
{
    const float* x     = (const float*)d_in[0];
    const float* W1    = (const float*)d_in[2];
    const float* b1    = (const float*)d_in[3];
    const float* W2    = (const float*)d_in[4];
    const float* b2    = (const float*)d_in[5];
    const float* G1    = (const float*)d_in[6];
    const float* gb1   = (const float*)d_in[7];
    const float* G2    = (const float*)d_in[8];
    const float* gb2   = (const float*)d_in[9];
    const float* gamma = (const float*)d_in[10];
    const float* beta  = (const float*)d_in[11];
    float* out = (float*)d_out;

    __half *pLC, *pGC, *pH, *pP, *pHg, *pS, *pWt;
    cudaGetSymbolAddress((void**)&pLC, g_LC);
    cudaGetSymbolAddress((void**)&pGC, g_GC);
    cudaGetSymbolAddress((void**)&pH,  g_H);
    cudaGetSymbolAddress((void**)&pP,  g_P);
    cudaGetSymbolAddress((void**)&pHg, g_Hg);
    cudaGetSymbolAddress((void**)&pS,  g_S);
    cudaGetSymbolAddress((void**)&pWt, g_Wt);
    __half* pW1t = pWt + 0 * (size_t)ND * ND;
    __half* pW2t = pWt + 1 * (size_t)ND * ND;
    __half* pG1t = pWt + 2 * (size_t)ND * ND;
    __half* pG2t = pWt + 3 * (size_t)ND * ND;

    cudaFuncSetAttribute(gemm_kernel<true >, cudaFuncAttributeMaxDynamicSharedMemorySize, SMEM_B);
    cudaFuncSetAttribute(gemm_kernel<false>, cudaFuncAttributeMaxDynamicSharedMemorySize, SMEM_B);

    // 1) weights + reductions, one launch (plain)
    prep_kernel<<<2048, 256>>>(x, W1, W2, G1, G2);

    // PDL attribute for dependent launches
    cudaLaunchAttribute pdl[1];
    pdl[0].id = cudaLaunchAttributeProgrammaticStreamSerialization;
    pdl[0].val.programmaticStreamSerializationAllowed = 1;

    const int mb_big = NROWS / 128, mb_sm = NB / 128;   // 384, 16

    // 2) stage 1 (mish): big + small fused
    {
        cudaLaunchConfig_t cfg = {};
        cfg.gridDim  = dim3(mb_big + mb_sm, 4);
        cfg.blockDim = dim3(256);
        cfg.dynamicSmemBytes = SMEM_B;
        cfg.stream = 0;
        cfg.attrs = pdl;
        cfg.numAttrs = 1;
        cudaLaunchKernelEx(&cfg, gemm_kernel<true>,
                           (const __half*)pLC, (const __half*)pW1t, b1, pH, mb_big,
                           (const __half*)pGC, (const __half*)pG1t, gb1, pHg);
    }

    // 3) stage 2 (linear): big + small fused
    {
        cudaLaunchConfig_t cfg = {};
        cfg.gridDim  = dim3(mb_big + mb_sm, 4);
        cfg.blockDim = dim3(256);
        cfg.dynamicSmemBytes = SMEM_B;
        cfg.stream = 0;
        cfg.attrs = pdl;
        cfg.numAttrs = 1;
        cudaLaunchKernelEx(&cfg, gemm_kernel<false>,
                           (const __half*)pH, (const __half*)pW2t, b2, pP, mb_big,
                           (const __half*)pHg, (const __half*)pG2t, gb2, pS);
    }

    // 4) combine + LayerNorm
    {
        cudaLaunchConfig_t cfg = {};
        cfg.gridDim  = dim3(NB * NCELLS / 8);
        cfg.blockDim = dim3(256);
        cfg.dynamicSmemBytes = 0;
        cfg.stream = 0;
        cfg.attrs = pdl;
        cfg.numAttrs = 1;
        cudaLaunchKernelEx(&cfg, ln_kernel, x, gamma, beta, (float*)out);
    }
}